// round 15
// baseline (speedup 1.0000x reference)
#include <cuda_runtime.h>
#include <math.h>
#include <stdint.h>

#define BB   16
#define NN   4096
#define DD   256
#define NSL  8
#define NPI  4
#define HH   256
#define SCALE_F 0.0625f
#define EPS_F   1e-8f

#define KTP 36
#define PQ  260
#define PV  264
#define RBUF 9216

#define AP   36
#define GBUF 9216

// out layout offsets
#define OUT_SEMSLOTS 0
#define OUT_SEMDOTS  32768
#define OUT_INSTSLOTS 557056
#define OUT_INSTDOTS  688128

// ---------------- scratch ----------------
__device__ uint32_t g_xi[BB*NN*DD];
__device__ uint32_t g_wt[2*DD*DD];
__device__ float g_k[BB*NN*DD];
__device__ float g_v[BB*NN*DD];

__device__ float g_sem_slots[BB*NSL*DD];
__device__ float g_sem_q[BB*NSL*DD];
__device__ float g_sem_dots[BB*NSL*NN];
__device__ float g_sem_rowsum[BB*NSL];
__device__ float g_sem_acc[BB*NSL*DD];

__device__ float g_inst_slots[BB*NSL*NPI*DD];
__device__ float g_inst_q[BB*NSL*NPI*DD];
__device__ float g_inst_rowsum[BB*NSL*NPI];
__device__ float g_inst_acc[BB*NSL*NPI*DD];

// ---------------- helpers ----------------
__device__ __forceinline__ float warp_sum(float v) {
#pragma unroll
    for (int o = 16; o; o >>= 1) v += __shfl_xor_sync(0xffffffffu, v, o);
    return v;
}

__device__ __forceinline__ void block_stats(float v, float* rs, float* rs2, int t,
                                            float& m, float& inv) {
    float s  = warp_sum(v);
    float s2 = warp_sum(v * v);
    if ((t & 31) == 0) { rs[t >> 5] = s; rs2[t >> 5] = s2; }
    __syncthreads();
    float sum = 0.f, sum2 = 0.f;
#pragma unroll
    for (int i = 0; i < 8; i++) { sum += rs[i]; sum2 += rs2[i]; }
    m = sum * (1.0f / 256.0f);
    float var = sum2 * (1.0f / 256.0f) - m * m;
    inv = rsqrtf(var + 1e-5f);
    __syncthreads();
}

__device__ __forceinline__ uint32_t f2tf(float f) {
    uint32_t u;
    asm("cvt.rna.tf32.f32 %0, %1;" : "=r"(u) : "f"(f));
    return u;
}

__device__ __forceinline__ void mma_tf32(float* c, const uint32_t* a, const uint32_t* b) {
    asm volatile("mma.sync.aligned.m16n8k8.row.col.f32.tf32.tf32.f32 "
        "{%0,%1,%2,%3}, {%4,%5,%6,%7}, {%8,%9}, {%0,%1,%2,%3};"
        : "+f"(c[0]), "+f"(c[1]), "+f"(c[2]), "+f"(c[3])
        : "r"(a[0]), "r"(a[1]), "r"(a[2]), "r"(a[3]), "r"(b[0]), "r"(b[1]));
}

__device__ __forceinline__ uint32_t smem_addr_u32(const void* p) {
    uint32_t a;
    asm("{ .reg .u64 tmp; cvta.to.shared.u64 tmp, %1; cvt.u32.u64 %0, tmp; }"
        : "=r"(a) : "l"(p));
    return a;
}

__device__ __forceinline__ void cpa16(uint32_t saddr, const void* g) {
    asm volatile("cp.async.cg.shared.global [%0], [%1], 16;" :: "r"(saddr), "l"(g));
}
#define CPA_COMMIT() asm volatile("cp.async.commit_group;" ::: "memory")
#define CPA_WAIT(n)  asm volatile("cp.async.wait_group %0;" :: "n"(n) : "memory")

// ---------------- 1) LN over inputs -> tf32 bits ----------------
__global__ void __launch_bounds__(256) ln_input_kernel(const float* __restrict__ x,
                                                       const float* __restrict__ g,
                                                       const float* __restrict__ b) {
    __shared__ float rs[8], rs2[8];
    int row = blockIdx.x;
    int t   = threadIdx.x;
    float v = x[(size_t)row * DD + t];
    float m, inv;
    block_stats(v, rs, rs2, t, m, inv);
    g_xi[(size_t)row * DD + t] = f2tf((v - m) * inv * g[t] + b[t]);
}

// ---------------- 1b) transpose W -> g_wt[mat][n][k] tf32 ----------------
__global__ void __launch_bounds__(256) prep_b_kernel(const float* __restrict__ Wk,
                                                     const float* __restrict__ Wv) {
    __shared__ float tile[32][33];
    int bi = blockIdx.x;
    int mat = bi >> 6;
    int tid = bi & 63;
    int tn0 = (tid & 7) * 32;
    int tk0 = (tid >> 3) * 32;
    const float* W = mat ? Wv : Wk;
    int t = threadIdx.x;
    int c = t & 31, r = t >> 5;
#pragma unroll
    for (int j = 0; j < 4; j++) {
        int kl = r + j * 8;
        tile[c][kl] = W[(size_t)(tk0 + kl) * DD + tn0 + c];
    }
    __syncthreads();
#pragma unroll
    for (int j = 0; j < 4; j++) {
        int nl = r + j * 8;
        g_wt[(size_t)mat * DD * DD + (size_t)(tn0 + nl) * DD + tk0 + c] = f2tf(tile[nl][c]);
    }
}

// ---------------- 2) TF32 GEMM (cp.async, 3 CTAs/SM) ----------------
__global__ void __launch_bounds__(256, 3) gemm_tf32_kernel(const float* __restrict__ bk,
                                                           const float* __restrict__ bv) {
    extern __shared__ uint32_t smu[];

    int t = threadIdx.x;
    int mat = blockIdx.x >> 1;
    const float* bias = mat ? bv : bk;
    float* C          = mat ? g_v : g_k;
    int nbase = (blockIdx.x & 1) * 128;
    size_t mbase = (size_t)blockIdx.y * 128;

    int wid = t >> 5, lane = t & 31;
    int wm = (wid >> 1) * 32;
    int wn = (wid & 1) * 64;
    int qrow = lane >> 2;
    int qk   = lane & 3;

    float c[2][8][4];
#pragma unroll
    for (int mt = 0; mt < 2; mt++)
#pragma unroll
        for (int nt = 0; nt < 8; nt++)
#pragma unroll
            for (int i = 0; i < 4; i++) c[mt][nt][i] = 0.f;

    int srow = t >> 1;
    int sc4  = (t & 1) * 16;
    const uint32_t* agp = g_xi + (mbase + srow) * 256 + sc4;
    const uint32_t* bgp = g_wt + (size_t)mat * DD * DD + (size_t)(nbase + srow) * 256 + sc4;
    uint32_t sbase = smem_addr_u32(smu);
    uint32_t dstoff = (uint32_t)(srow * AP + sc4) * 4;

    auto stage = [&](int bsel, int cc) {
        uint32_t abuf = sbase + (uint32_t)bsel * GBUF * 4 + dstoff;
        uint32_t bbuf = abuf + 4608u * 4;
        const uint32_t* ag = agp + cc * 32;
        const uint32_t* bg = bgp + cc * 32;
#pragma unroll
        for (int j = 0; j < 4; j++) {
            cpa16(abuf + j * 16, ag + j * 4);
            cpa16(bbuf + j * 16, bg + j * 4);
        }
        CPA_COMMIT();
    };

    stage(0, 0);
    stage(1, 1);

#pragma unroll 1
    for (int cc = 0; cc < 8; cc++) {
        if (cc < 7) CPA_WAIT(1); else CPA_WAIT(0);
        __syncthreads();
        const uint32_t* As = smu + (cc & 1) * GBUF;
        const uint32_t* Bs = As + 4608;
#pragma unroll
        for (int k8 = 0; k8 < 4; k8++) {
            int kb = k8 * 8 + qk;
            uint32_t a[2][4], b[8][2];
#pragma unroll
            for (int mt = 0; mt < 2; mt++) {
                int m = wm + mt * 16 + qrow;
                a[mt][0] = As[m * AP + kb];
                a[mt][1] = As[(m + 8) * AP + kb];
                a[mt][2] = As[m * AP + kb + 4];
                a[mt][3] = As[(m + 8) * AP + kb + 4];
            }
#pragma unroll
            for (int nt = 0; nt < 8; nt++) {
                int n = wn + nt * 8 + qrow;
                b[nt][0] = Bs[n * AP + kb];
                b[nt][1] = Bs[n * AP + kb + 4];
            }
#pragma unroll
            for (int mt = 0; mt < 2; mt++)
#pragma unroll
                for (int nt = 0; nt < 8; nt++)
                    mma_tf32(c[mt][nt], a[mt], b[nt]);
        }
        __syncthreads();
        if (cc + 2 < 8) stage(cc & 1, cc + 2);
    }

#pragma unroll
    for (int mt = 0; mt < 2; mt++) {
        int r0 = wm + mt * 16 + qrow;
#pragma unroll
        for (int nt = 0; nt < 8; nt++) {
            int col = nbase + wn + nt * 8 + 2 * qk;
            float b0v = bias[col], b1v = bias[col + 1];
            size_t base0 = (mbase + r0) * 256 + col;
            size_t base1 = (mbase + r0 + 8) * 256 + col;
            *(float2*)(C + base0) = make_float2(c[mt][nt][0] + b0v, c[mt][nt][1] + b1v);
            *(float2*)(C + base1) = make_float2(c[mt][nt][2] + b0v, c[mt][nt][3] + b1v);
        }
    }
}

// ---------------- 3) init kernels ----------------
__global__ void sem_init_kernel(const float* __restrict__ mu) {
    int r = blockIdx.x;
    int i = r & 7;
    g_sem_slots[(size_t)r * DD + threadIdx.x] = mu[i * DD + threadIdx.x];
}

__global__ void inst_init_kernel(const float* __restrict__ mu,
                                 const float* __restrict__ sigma,
                                 const float* __restrict__ noise) {
    size_t idx = (size_t)blockIdx.x * 256 + threadIdx.x;
    int d = idx & 255;
    int s = (idx >> 10) & 7;
    g_inst_slots[idx] = mu[s * DD + d] + expf(sigma[s * DD + d]) * noise[idx];
}

// ---------------- 4) double-buffered staged GEMV (4 rows/block) ----------------
__device__ __forceinline__ void gemm4_staged(const float* __restrict__ W,
                                             const float (*__restrict__ in)[DD],
                                             float (*__restrict__ ws)[16][DD],
                                             float* o, int t) {
    o[0] = o[1] = o[2] = o[3] = 0.f;
    int r0 = t >> 6;
    int c0 = (t & 63) * 4;
    float4 pre[4];

#pragma unroll
    for (int j = 0; j < 4; j++)
        pre[j] = *(const float4*)(W + (size_t)(r0 + j * 4) * DD + c0);
#pragma unroll
    for (int j = 0; j < 4; j++)
        *(float4*)&ws[0][r0 + j * 4][c0] = pre[j];
#pragma unroll
    for (int j = 0; j < 4; j++)
        pre[j] = *(const float4*)(W + (size_t)(16 + r0 + j * 4) * DD + c0);
    __syncthreads();

#pragma unroll 1
    for (int ti = 0; ti < 16; ti++) {
        int cur = ti & 1;
        if (ti + 1 < 16) {
#pragma unroll
            for (int j = 0; j < 4; j++)
                *(float4*)&ws[cur ^ 1][r0 + j * 4][c0] = pre[j];
        }
        if (ti + 2 < 16) {
            int d0 = (ti + 2) * 16;
#pragma unroll
            for (int j = 0; j < 4; j++)
                pre[j] = *(const float4*)(W + (size_t)(d0 + r0 + j * 4) * DD + c0);
        }
        int db = ti * 16;
#pragma unroll
        for (int j4 = 0; j4 < 16; j4 += 4) {
            float w0 = ws[cur][j4 + 0][t];
            float w1 = ws[cur][j4 + 1][t];
            float w2 = ws[cur][j4 + 2][t];
            float w3 = ws[cur][j4 + 3][t];
#pragma unroll
            for (int r = 0; r < 4; r++) {
                float4 sv = *(const float4*)&in[r][db + j4];
                o[r] += sv.x * w0 + sv.y * w1 + sv.z * w2 + sv.w * w3;
            }
        }
        __syncthreads();
    }
}

// ---------------- 5) fused MLP + Q + zero (+ optional out sink) ----------------
template<bool DO_MLP, bool DO_Q>
__global__ void __launch_bounds__(256) mlpq_kernel(
    int which, float* __restrict__ out_slots,
    const float* __restrict__ lnff_g, const float* __restrict__ lnff_b,
    const float* __restrict__ W1, const float* __restrict__ b1,
    const float* __restrict__ W2, const float* __restrict__ b2,
    const float* __restrict__ lns_g, const float* __restrict__ lns_b,
    const float* __restrict__ Wq, const float* __restrict__ bq)
{
    __shared__ float s1[4][DD];
    __shared__ float sln[4][DD];
    __shared__ float hs[4][DD];
    __shared__ float ws[2][16][DD];
    __shared__ float rs[8], rs2[8];

    float* slots  = which ? g_inst_slots  : g_sem_slots;
    float* q      = which ? g_inst_q      : g_sem_q;
    float* acc    = which ? g_inst_acc    : g_sem_acc;
    float* rowsum = which ? g_inst_rowsum : g_sem_rowsum;

    int t  = threadIdx.x;
    int r0 = blockIdx.x * 4;

    if (DO_MLP) {
        float gg = lnff_g[t], bb = lnff_b[t];
#pragma unroll
        for (int r = 0; r < 4; r++) {
            int row = r0 + r;
            float v = slots[(size_t)row * DD + t] + acc[(size_t)row * DD + t] / rowsum[row];
            s1[r][t] = v;
            float m, inv;
            block_stats(v, rs, rs2, t, m, inv);
            sln[r][t] = (v - m) * inv * gg + bb;
        }
        __syncthreads();
        float h[4];
        gemm4_staged(W1, sln, ws, h, t);
        float b1v = b1[t];
#pragma unroll
        for (int r = 0; r < 4; r++) hs[r][t] = fmaxf(h[r] + b1v, 0.f);
        __syncthreads();
        float o[4];
        gemm4_staged(W2, hs, ws, o, t);
        float b2v = b2[t];
#pragma unroll
        for (int r = 0; r < 4; r++) {
            float nv = s1[r][t] + o[r] + b2v;
            slots[(size_t)(r0 + r) * DD + t] = nv;
            if (out_slots) out_slots[(size_t)(r0 + r) * DD + t] = nv;
            s1[r][t] = nv;
        }
    } else {
#pragma unroll
        for (int r = 0; r < 4; r++) s1[r][t] = slots[(size_t)(r0 + r) * DD + t];
    }

    if (DO_Q) {
        float gg = lns_g[t], bb = lns_b[t];
#pragma unroll
        for (int r = 0; r < 4; r++) {
            int row = r0 + r;
            float v = s1[r][t];
            float m, inv;
            block_stats(v, rs, rs2, t, m, inv);
            sln[r][t] = (v - m) * inv * gg + bb;
            acc[(size_t)row * DD + t] = 0.f;
            if (t == 0) rowsum[row] = 0.f;
        }
        __syncthreads();
        float qa[4];
        gemm4_staged(Wq, sln, ws, qa, t);
        float qb = bq[t];
#pragma unroll
        for (int r = 0; r < 4; r++)
            q[(size_t)(r0 + r) * DD + t] = qa[r] + qb;
    }
}

// ---------------- mma phase helpers ----------------
template<int MT>
__device__ __forceinline__ void dots_phase(const float* __restrict__ kbase,
                                           const float* __restrict__ qs,
                                           float* __restrict__ kt,
                                           float c[MT][4][4], int t) {
    int lane = t & 31, wid = t >> 5;
    int qrow = lane >> 2, qk = lane & 3;
    int wn = wid * 32;
#pragma unroll
    for (int mt = 0; mt < MT; mt++)
#pragma unroll
        for (int nt = 0; nt < 4; nt++)
#pragma unroll
            for (int i = 0; i < 4; i++) c[mt][nt][i] = 0.f;

    const uint32_t* qsu = (const uint32_t*)qs;
    int srow = t >> 3;
    int sc4  = (t & 7) * 4;

    float4 pre[8];
#pragma unroll
    for (int j = 0; j < 8; j++)
        pre[j] = *(const float4*)(kbase + (size_t)(srow + j * 32) * DD + sc4);
    {
#pragma unroll
        for (int j = 0; j < 8; j++) {
            uint32_t* dst = (uint32_t*)&kt[(srow + j * 32) * KTP + sc4];
            dst[0] = f2tf(pre[j].x); dst[1] = f2tf(pre[j].y);
            dst[2] = f2tf(pre[j].z); dst[3] = f2tf(pre[j].w);
        }
#pragma unroll
        for (int j = 0; j < 8; j++)
            pre[j] = *(const float4*)(kbase + (size_t)(srow + j * 32) * DD + 32 + sc4);
    }
    __syncthreads();

#pragma unroll 1
    for (int cc = 0; cc < 8; cc++) {
        const uint32_t* ktu = (const uint32_t*)(kt + (cc & 1) * RBUF);
        if (cc + 1 < 8) {
            float* nxt = kt + ((cc + 1) & 1) * RBUF;
#pragma unroll
            for (int j = 0; j < 8; j++) {
                uint32_t* dst = (uint32_t*)&nxt[(srow + j * 32) * KTP + sc4];
                dst[0] = f2tf(pre[j].x); dst[1] = f2tf(pre[j].y);
                dst[2] = f2tf(pre[j].z); dst[3] = f2tf(pre[j].w);
            }
        }
        if (cc + 2 < 8) {
            int dc = (cc + 2) * 32;
#pragma unroll
            for (int j = 0; j < 8; j++)
                pre[j] = *(const float4*)(kbase + (size_t)(srow + j * 32) * DD + dc + sc4);
        }
        int dc = cc * 32;
#pragma unroll
        for (int k8 = 0; k8 < 4; k8++) {
            uint32_t a[MT][4], b[4][2];
            int kg = dc + k8 * 8 + qk;
            int kl = k8 * 8 + qk;
#pragma unroll
            for (int mt = 0; mt < MT; mt++) {
                int m0 = mt * 16 + qrow;
                a[mt][0] = qsu[m0 * PQ + kg];
                a[mt][1] = qsu[(m0 + 8) * PQ + kg];
                a[mt][2] = qsu[m0 * PQ + kg + 4];
                a[mt][3] = qsu[(m0 + 8) * PQ + kg + 4];
            }
#pragma unroll
            for (int nt = 0; nt < 4; nt++) {
                int n = wn + nt * 8 + qrow;
                b[nt][0] = ktu[n * KTP + kl];
                b[nt][1] = ktu[n * KTP + kl + 4];
            }
#pragma unroll
            for (int mt = 0; mt < MT; mt++)
#pragma unroll
                for (int nt = 0; nt < 4; nt++)
                    mma_tf32(c[mt][nt], a[mt], b[nt]);
        }
        __syncthreads();
    }
}

template<int MT, int PD>
__device__ __forceinline__ void store_dots(float c[MT][4][4], float* __restrict__ dotm, int t) {
    int lane = t & 31, wid = t >> 5;
    int qrow = lane >> 2, qk = lane & 3;
    int wn = wid * 32;
#pragma unroll
    for (int mt = 0; mt < MT; mt++)
#pragma unroll
        for (int nt = 0; nt < 4; nt++) {
            int tok = wn + nt * 8 + 2 * qk;
            int m0  = mt * 16 + qrow;
            dotm[tok * PD + m0]           = c[mt][nt][0] * SCALE_F;
            dotm[(tok + 1) * PD + m0]     = c[mt][nt][1] * SCALE_F;
            dotm[tok * PD + m0 + 8]       = c[mt][nt][2] * SCALE_F;
            dotm[(tok + 1) * PD + m0 + 8] = c[mt][nt][3] * SCALE_F;
        }
}

template<int MT>
__device__ __forceinline__ void upd_phase(const float* __restrict__ vbase,
                                          const float* __restrict__ atm,
                                          float* __restrict__ vt,
                                          float c[MT][4][4], int t) {
    int lane = t & 31, wid = t >> 5;
    int qrow = lane >> 2, qk = lane & 3;
    int wd = wid * 32;
#pragma unroll
    for (int mt = 0; mt < MT; mt++)
#pragma unroll
        for (int nt = 0; nt < 4; nt++)
#pragma unroll
            for (int i = 0; i < 4; i++) c[mt][nt][i] = 0.f;

    const uint32_t* au = (const uint32_t*)atm;
    int srow = t >> 6;
    int sc4  = (t & 63) * 4;

    float4 pre[8];
#pragma unroll
    for (int j = 0; j < 8; j++)
        pre[j] = *(const float4*)(vbase + (size_t)(srow + j * 4) * DD + sc4);
    {
#pragma unroll
        for (int j = 0; j < 8; j++) {
            uint32_t* dst = (uint32_t*)&vt[(srow + j * 4) * PV + sc4];
            dst[0] = f2tf(pre[j].x); dst[1] = f2tf(pre[j].y);
            dst[2] = f2tf(pre[j].z); dst[3] = f2tf(pre[j].w);
        }
#pragma unroll
        for (int j = 0; j < 8; j++)
            pre[j] = *(const float4*)(vbase + (size_t)(32 + srow + j * 4) * DD + sc4);
    }
    __syncthreads();

#pragma unroll 1
    for (int cc = 0; cc < 8; cc++) {
        const uint32_t* vu = (const uint32_t*)(vt + (cc & 1) * RBUF);
        if (cc + 1 < 8) {
            float* nxt = vt + ((cc + 1) & 1) * RBUF;
#pragma unroll
            for (int j = 0; j < 8; j++) {
                uint32_t* dst = (uint32_t*)&nxt[(srow + j * 4) * PV + sc4];
                dst[0] = f2tf(pre[j].x); dst[1] = f2tf(pre[j].y);
                dst[2] = f2tf(pre[j].z); dst[3] = f2tf(pre[j].w);
            }
        }
        if (cc + 2 < 8) {
            int tc = (cc + 2) * 32;
#pragma unroll
            for (int j = 0; j < 8; j++)
                pre[j] = *(const float4*)(vbase + (size_t)(tc + srow + j * 4) * DD + sc4);
        }
        int tc = cc * 32;
#pragma unroll
        for (int k8 = 0; k8 < 4; k8++) {
            uint32_t a[MT][4], b[4][2];
            int kg = tc + k8 * 8 + qk;
            int kl = k8 * 8 + qk;
#pragma unroll
            for (int mt = 0; mt < MT; mt++) {
                int m0 = mt * 16 + qrow;
                a[mt][0] = au[m0 * PQ + kg];
                a[mt][1] = au[(m0 + 8) * PQ + kg];
                a[mt][2] = au[m0 * PQ + kg + 4];
                a[mt][3] = au[(m0 + 8) * PQ + kg + 4];
            }
#pragma unroll
            for (int nt = 0; nt < 4; nt++) {
                int d = wd + nt * 8 + qrow;
                b[nt][0] = vu[kl * PV + d];
                b[nt][1] = vu[(kl + 4) * PV + d];
            }
#pragma unroll
            for (int mt = 0; mt < MT; mt++)
#pragma unroll
                for (int nt = 0; nt < 4; nt++)
                    mma_tf32(c[mt][nt], a[mt], b[nt]);
        }
        __syncthreads();
    }
}

template<int MT, int NRS>
__device__ __forceinline__ void upd_atomics(float c[MT][4][4], float* __restrict__ gacc,
                                            int slot_base, int t) {
    int lane = t & 31, wid = t >> 5;
    int qrow = lane >> 2, qk = lane & 3;
    int wd = wid * 32;
#pragma unroll
    for (int mt = 0; mt < MT; mt++)
#pragma unroll
        for (int nt = 0; nt < 4; nt++) {
            int d  = wd + nt * 8 + 2 * qk;
            int s0 = mt * 16 + qrow;
            atomicAdd(&gacc[(size_t)(slot_base + s0) * DD + d],     c[mt][nt][0]);
            atomicAdd(&gacc[(size_t)(slot_base + s0) * DD + d + 1], c[mt][nt][1]);
            if (s0 + 8 < NRS) {
                atomicAdd(&gacc[(size_t)(slot_base + s0 + 8) * DD + d],     c[mt][nt][2]);
                atomicAdd(&gacc[(size_t)(slot_base + s0 + 8) * DD + d + 1], c[mt][nt][3]);
            }
        }
}

// ---------------- 6) fused sem (mma) ----------------
__global__ void __launch_bounds__(256) sem_fused_kernel(float* __restrict__ out_dots) {
    extern __shared__ float smem[];
    float* qs   = smem;
    float* reg2 = smem + 16 * PQ;
    const int PD = 17;

    int b  = blockIdx.y;
    int n0 = blockIdx.x * 256;
    int t  = threadIdx.x;
    int n  = n0 + t;

    for (int idx = t; idx < NSL * DD; idx += 256) {
        int r = idx >> 8, cc = idx & 255;
        ((uint32_t*)qs)[r * PQ + cc] = f2tf(g_sem_q[(size_t)b * NSL * DD + idx]);
    }
    for (int idx = t; idx < 8 * DD; idx += 256) {
        int r = idx >> 8, cc = idx & 255;
        qs[(NSL + r) * PQ + cc] = 0.f;
    }

    float c[1][4][4];
    dots_phase<1>(g_k + ((size_t)b * NN + n0) * DD, qs, reg2, c, t);

    store_dots<1, PD>(c, reg2, t);
    __syncthreads();

    float dv[NSL], e[NSL];
    float mx = -1e30f;
#pragma unroll
    for (int i = 0; i < NSL; i++) { dv[i] = reg2[t * PD + i]; mx = fmaxf(mx, dv[i]); }
    float ssum = 0.f;
#pragma unroll
    for (int i = 0; i < NSL; i++) { e[i] = expf(dv[i] - mx); ssum += e[i]; }
    float inv = 1.0f / ssum;

    size_t base = (size_t)b * NSL * NN + n;
    int l = t & 31;
    float at[NSL];
#pragma unroll
    for (int i = 0; i < NSL; i++) {
        at[i] = e[i] * inv + EPS_F;
        if (out_dots) {
            g_sem_dots[base + (size_t)i * NN] = dv[i];
            out_dots[base + (size_t)i * NN]   = dv[i];
        }
        float sv = warp_sum(at[i]);
        if (l == 0) atomicAdd(&g_sem_rowsum[b * NSL + i], sv);
    }

    __syncthreads();
#pragma unroll
    for (int i = 0; i < NSL; i++)
        ((uint32_t*)qs)[i * PQ + t] = f2tf(at[i]);
#pragma unroll
    for (int i = NSL; i < 16; i++)
        qs[i * PQ + t] = 0.f;
    __syncthreads();

    float c2[1][4][4];
    upd_phase<1>(g_v + ((size_t)b * NN + n0) * DD, qs, reg2, c2, t);
    upd_atomics<1, NSL>(c2, g_sem_acc, b * NSL, t);
}

// ---------------- 7) fused inst (mma) ----------------
__global__ void __launch_bounds__(256) inst_fused_kernel(float* __restrict__ out_dots) {
    extern __shared__ float smem[];
    float* qs   = smem;
    float* reg2 = smem + 32 * PQ;
    const int PD = 33;

    int b  = blockIdx.y;
    int n0 = blockIdx.x * 256;
    int t  = threadIdx.x;
    int n  = n0 + t;

    for (int idx = t; idx < 32 * DD; idx += 256) {
        int r = idx >> 8, cc = idx & 255;
        ((uint32_t*)qs)[r * PQ + cc] = f2tf(g_inst_q[(size_t)b * 32 * DD + idx]);
    }

    float c[2][4][4];
    dots_phase<2>(g_k + ((size_t)b * NN + n0) * DD, qs, reg2, c, t);

    store_dots<2, PD>(c, reg2, t);
    __syncthreads();

    float wv[NSL];
    {
        size_t sbase = (size_t)b * NSL * NN + n;
        float sdv[NSL];
        float smx = -1e30f;
#pragma unroll
        for (int i = 0; i < NSL; i++) { sdv[i] = g_sem_dots[sbase + (size_t)i * NN]; smx = fmaxf(smx, sdv[i]); }
        float ss = 0.f;
#pragma unroll
        for (int i = 0; i < NSL; i++) { sdv[i] = expf(sdv[i] - smx); ss += sdv[i]; }
        float sinv = 1.0f / ss;
#pragma unroll
        for (int i = 0; i < NSL; i++) wv[i] = sdv[i] * sinv;
    }

    size_t dbase = (size_t)b * 32 * NN + n;
    int l = t & 31;
    float at[32];
#pragma unroll
    for (int s = 0; s < 8; s++) {
        float dv[NPI], e[NPI];
        float mx = -1e30f;
#pragma unroll
        for (int p = 0; p < NPI; p++) { dv[p] = reg2[t * PD + s * 4 + p]; mx = fmaxf(mx, dv[p]); }
        float ssum = 0.f;
#pragma unroll
        for (int p = 0; p < NPI; p++) { e[p] = expf(dv[p] - mx); ssum += e[p]; }
        float invs = 1.0f / ssum;
#pragma unroll
        for (int p = 0; p < NPI; p++) {
            int sp = s * 4 + p;
            at[sp] = (e[p] * invs + EPS_F) * wv[s];
            if (out_dots) out_dots[dbase + (size_t)sp * NN] = dv[p];
            float sv = warp_sum(at[sp]);
            if (l == 0) atomicAdd(&g_inst_rowsum[b * 32 + sp], sv);
        }
    }

    __syncthreads();
#pragma unroll
    for (int i = 0; i < 32; i++)
        ((uint32_t*)qs)[i * PQ + t] = f2tf(at[i]);
    __syncthreads();

    float c2[2][4][4];
    upd_phase<2>(g_v + ((size_t)b * NN + n0) * DD, qs, reg2, c2, t);
    upd_atomics<2, 32>(c2, g_inst_acc, b * 32, t);
}

// ---------------- launch ----------------
extern "C" void kernel_launch(void* const* d_in, const int* in_sizes, int n_in,
                              void* d_out, int out_size) {
    (void)in_sizes; (void)n_in; (void)out_size;
    const float* inputs      = (const float*)d_in[0];
    const float* noise       = (const float*)d_in[3];
    const float* ln_in_g     = (const float*)d_in[4];
    const float* ln_in_b     = (const float*)d_in[5];
    const float* ln_s_g      = (const float*)d_in[6];
    const float* ln_s_b      = (const float*)d_in[7];
    const float* ln_ff_g     = (const float*)d_in[8];
    const float* ln_ff_b     = (const float*)d_in[9];
    const float* slots_mu    = (const float*)d_in[10];
    const float* slots_sigma = (const float*)d_in[11];
    const float* Wq          = (const float*)d_in[12];
    const float* bq          = (const float*)d_in[13];
    const float* Wk          = (const float*)d_in[14];
    const float* bk          = (const float*)d_in[15];
    const float* Wv          = (const float*)d_in[16];
    const float* bv          = (const float*)d_in[17];
    const float* W1          = (const float*)d_in[18];
    const float* b1          = (const float*)d_in[19];
    const float* W2          = (const float*)d_in[20];
    const float* b2          = (const float*)d_in[21];
    float* out = (float*)d_out;

    const int sem_smem  = (16 * PQ + 2 * RBUF) * 4;
    const int inst_smem = (32 * PQ + 2 * RBUF) * 4;
    const int gemm_smem = 2 * GBUF * 4;
    static int attr_done = 0;
    if (!attr_done) {
        cudaFuncSetAttribute(sem_fused_kernel,  cudaFuncAttributeMaxDynamicSharedMemorySize, sem_smem);
        cudaFuncSetAttribute(inst_fused_kernel, cudaFuncAttributeMaxDynamicSharedMemorySize, inst_smem);
        cudaFuncSetAttribute(gemm_tf32_kernel,  cudaFuncAttributeMaxDynamicSharedMemorySize, gemm_smem);
        attr_done = 1;
    }

    // keep the profiled launch (index 3) = projection GEMM
    prep_b_kernel<<<128, 256>>>(Wk, Wv);
    ln_input_kernel<<<BB * NN, 256>>>(inputs, ln_in_g, ln_in_b);
    sem_init_kernel<<<BB * NSL, 256>>>(slots_mu);

    dim3 gemm_grid(4, 512);
    gemm_tf32_kernel<<<gemm_grid, 256, gemm_smem>>>(bk, bv);

    dim3 bn_grid(16, 16);
    const int SEM_BLKS  = BB * NSL / 4;        // 32
    const int INST_BLKS = BB * NSL * NPI / 4;  // 128

    mlpq_kernel<false, true><<<SEM_BLKS, 256>>>(0, nullptr, ln_ff_g, ln_ff_b, W1, b1, W2, b2,
                                                ln_s_g, ln_s_b, Wq, bq);
    for (int it = 0; it < 3; it++) {
        sem_fused_kernel<<<bn_grid, 256, sem_smem>>>(it == 2 ? out + OUT_SEMDOTS : nullptr);
        if (it < 2)
            mlpq_kernel<true, true><<<SEM_BLKS, 256>>>(0, nullptr, ln_ff_g, ln_ff_b, W1, b1, W2, b2,
                                                       ln_s_g, ln_s_b, Wq, bq);
        else
            mlpq_kernel<true, false><<<SEM_BLKS, 256>>>(0, out + OUT_SEMSLOTS, ln_ff_g, ln_ff_b,
                                                        W1, b1, W2, b2, ln_s_g, ln_s_b, Wq, bq);
    }

    inst_init_kernel<<<BB * NSL * NPI, 256>>>(slots_mu, slots_sigma, noise);

    mlpq_kernel<false, true><<<INST_BLKS, 256>>>(1, nullptr, ln_ff_g, ln_ff_b, W1, b1, W2, b2,
                                                 ln_s_g, ln_s_b, Wq, bq);
    for (int it = 0; it < 3; it++) {
        inst_fused_kernel<<<bn_grid, 256, inst_smem>>>(it == 2 ? out + OUT_INSTDOTS : nullptr);
        if (it < 2)
            mlpq_kernel<true, true><<<INST_BLKS, 256>>>(1, nullptr, ln_ff_g, ln_ff_b, W1, b1, W2, b2,
                                                        ln_s_g, ln_s_b, Wq, bq);
        else
            mlpq_kernel<true, false><<<INST_BLKS, 256>>>(1, out + OUT_INSTSLOTS, ln_ff_g, ln_ff_b,
                                                         W1, b1, W2, b2, ln_s_g, ln_s_b, Wq, bq);
    }
}

// round 17
// speedup vs baseline: 1.0409x; 1.0409x over previous
#include <cuda_runtime.h>
#include <math.h>
#include <stdint.h>

#define BB   16
#define NN   4096
#define DD   256
#define NSL  8
#define NPI  4
#define HH   256
#define SCALE_F 0.0625f
#define EPS_F   1e-8f

#define KTP 36
#define PQ  260
#define PV  264
#define RBUF 9216

#define AP   36
#define GBUF 9216   // u32 per gemm buffer (As 4608 + Bs 4608)

// out layout offsets
#define OUT_SEMSLOTS 0
#define OUT_SEMDOTS  32768
#define OUT_INSTSLOTS 557056
#define OUT_INSTDOTS  688128

// ---------------- scratch ----------------
__device__ uint32_t g_xi[BB*NN*DD];
__device__ uint32_t g_wt[2*DD*DD];
__device__ float g_k[BB*NN*DD];
__device__ float g_v[BB*NN*DD];

__device__ float g_sem_slots[BB*NSL*DD];
__device__ float g_sem_q[BB*NSL*DD];
__device__ float g_sem_dots[BB*NSL*NN];
__device__ float g_sem_rowsum[BB*NSL];
__device__ float g_sem_acc[BB*NSL*DD];

__device__ float g_inst_slots[BB*NSL*NPI*DD];
__device__ float g_inst_q[BB*NSL*NPI*DD];
__device__ float g_inst_rowsum[BB*NSL*NPI];
__device__ float g_inst_acc[BB*NSL*NPI*DD];

// ---------------- helpers ----------------
__device__ __forceinline__ float warp_sum(float v) {
#pragma unroll
    for (int o = 16; o; o >>= 1) v += __shfl_xor_sync(0xffffffffu, v, o);
    return v;
}

__device__ __forceinline__ void block_stats(float v, float* rs, float* rs2, int t,
                                            float& m, float& inv) {
    float s  = warp_sum(v);
    float s2 = warp_sum(v * v);
    if ((t & 31) == 0) { rs[t >> 5] = s; rs2[t >> 5] = s2; }
    __syncthreads();
    float sum = 0.f, sum2 = 0.f;
#pragma unroll
    for (int i = 0; i < 8; i++) { sum += rs[i]; sum2 += rs2[i]; }
    m = sum * (1.0f / 256.0f);
    float var = sum2 * (1.0f / 256.0f) - m * m;
    inv = rsqrtf(var + 1e-5f);
    __syncthreads();
}

__device__ __forceinline__ uint32_t f2tf(float f) {
    uint32_t u;
    asm("cvt.rna.tf32.f32 %0, %1;" : "=r"(u) : "f"(f));
    return u;
}

__device__ __forceinline__ void mma_tf32(float* c, const uint32_t* a, const uint32_t* b) {
    asm volatile("mma.sync.aligned.m16n8k8.row.col.f32.tf32.tf32.f32 "
        "{%0,%1,%2,%3}, {%4,%5,%6,%7}, {%8,%9}, {%0,%1,%2,%3};"
        : "+f"(c[0]), "+f"(c[1]), "+f"(c[2]), "+f"(c[3])
        : "r"(a[0]), "r"(a[1]), "r"(a[2]), "r"(a[3]), "r"(b[0]), "r"(b[1]));
}

__device__ __forceinline__ uint32_t smem_addr_u32(const void* p) {
    uint32_t a;
    asm("{ .reg .u64 tmp; cvta.to.shared.u64 tmp, %1; cvt.u32.u64 %0, tmp; }"
        : "=r"(a) : "l"(p));
    return a;
}

__device__ __forceinline__ void cpa16(uint32_t saddr, const void* g) {
    asm volatile("cp.async.cg.shared.global [%0], [%1], 16;" :: "r"(saddr), "l"(g));
}
#define CPA_COMMIT() asm volatile("cp.async.commit_group;" ::: "memory")
#define CPA_WAIT(n)  asm volatile("cp.async.wait_group %0;" :: "n"(n) : "memory")

// ---------------- 1) LN over inputs -> tf32 bits ----------------
__global__ void __launch_bounds__(256) ln_input_kernel(const float* __restrict__ x,
                                                       const float* __restrict__ g,
                                                       const float* __restrict__ b) {
    __shared__ float rs[8], rs2[8];
    int row = blockIdx.x;
    int t   = threadIdx.x;
    float v = x[(size_t)row * DD + t];
    float m, inv;
    block_stats(v, rs, rs2, t, m, inv);
    g_xi[(size_t)row * DD + t] = f2tf((v - m) * inv * g[t] + b[t]);
}

// ---------------- 1b) transpose W -> g_wt[mat][n][k] tf32 ----------------
__global__ void __launch_bounds__(256) prep_b_kernel(const float* __restrict__ Wk,
                                                     const float* __restrict__ Wv) {
    __shared__ float tile[32][33];
    int bi = blockIdx.x;
    int mat = bi >> 6;
    int tid = bi & 63;
    int tn0 = (tid & 7) * 32;
    int tk0 = (tid >> 3) * 32;
    const float* W = mat ? Wv : Wk;
    int t = threadIdx.x;
    int c = t & 31, r = t >> 5;
#pragma unroll
    for (int j = 0; j < 4; j++) {
        int kl = r + j * 8;
        tile[c][kl] = W[(size_t)(tk0 + kl) * DD + tn0 + c];
    }
    __syncthreads();
#pragma unroll
    for (int j = 0; j < 4; j++) {
        int nl = r + j * 8;
        g_wt[(size_t)mat * DD * DD + (size_t)(tn0 + nl) * DD + tk0 + c] = f2tf(tile[nl][c]);
    }
}

// ---------------- 2) TF32 GEMM (cp.async 3-buffer ring, eager prefetch) ----------------
__global__ void __launch_bounds__(256) gemm_tf32_kernel(const float* __restrict__ bk,
                                                        const float* __restrict__ bv) {
    extern __shared__ uint32_t smu[];   // [3][GBUF]

    int t = threadIdx.x;
    int mat = blockIdx.x >> 1;
    const float* bias = mat ? bv : bk;
    float* C          = mat ? g_v : g_k;
    int nbase = (blockIdx.x & 1) * 128;
    size_t mbase = (size_t)blockIdx.y * 128;

    int wid = t >> 5, lane = t & 31;
    int wm = (wid >> 1) * 32;
    int wn = (wid & 1) * 64;
    int qrow = lane >> 2;
    int qk   = lane & 3;

    float c[2][8][4];
#pragma unroll
    for (int mt = 0; mt < 2; mt++)
#pragma unroll
        for (int nt = 0; nt < 8; nt++)
#pragma unroll
            for (int i = 0; i < 4; i++) c[mt][nt][i] = 0.f;

    int srow = t >> 1;
    int sc4  = (t & 1) * 16;
    const uint32_t* agp = g_xi + (mbase + srow) * 256 + sc4;
    const uint32_t* bgp = g_wt + (size_t)mat * DD * DD + (size_t)(nbase + srow) * 256 + sc4;
    uint32_t sbase = smem_addr_u32(smu);
    uint32_t dstoff = (uint32_t)(srow * AP + sc4) * 4;

    auto stage = [&](int bsel, int cc) {
        uint32_t abuf = sbase + (uint32_t)bsel * GBUF * 4 + dstoff;
        uint32_t bbuf = abuf + 4608u * 4;
        const uint32_t* ag = agp + cc * 32;
        const uint32_t* bg = bgp + cc * 32;
#pragma unroll
        for (int j = 0; j < 4; j++) {
            cpa16(abuf + j * 16, ag + j * 4);
            cpa16(bbuf + j * 16, bg + j * 4);
        }
        CPA_COMMIT();
    };

    stage(0, 0);
    stage(1, 1);

#pragma unroll 1
    for (int cc = 0; cc < 8; cc++) {
        // eager prefetch: loads for cc+2 are in flight DURING compute of cc
        if (cc + 2 < 8) {
            stage((cc + 2) % 3, cc + 2);
            CPA_WAIT(2);            // committed = cc+3, leave 2 pending -> chunk cc landed
        } else if (cc == 6) {
            CPA_WAIT(1);
        } else {
            CPA_WAIT(0);
        }
        __syncthreads();
        const uint32_t* As = smu + (cc % 3) * GBUF;
        const uint32_t* Bs = As + 4608;
#pragma unroll
        for (int k8 = 0; k8 < 4; k8++) {
            int kb = k8 * 8 + qk;
            uint32_t a[2][4], b[8][2];
#pragma unroll
            for (int mt = 0; mt < 2; mt++) {
                int m = wm + mt * 16 + qrow;
                a[mt][0] = As[m * AP + kb];
                a[mt][1] = As[(m + 8) * AP + kb];
                a[mt][2] = As[m * AP + kb + 4];
                a[mt][3] = As[(m + 8) * AP + kb + 4];
            }
#pragma unroll
            for (int nt = 0; nt < 8; nt++) {
                int n = wn + nt * 8 + qrow;
                b[nt][0] = Bs[n * AP + kb];
                b[nt][1] = Bs[n * AP + kb + 4];
            }
#pragma unroll
            for (int mt = 0; mt < 2; mt++)
#pragma unroll
                for (int nt = 0; nt < 8; nt++)
                    mma_tf32(c[mt][nt], a[mt], b[nt]);
        }
        __syncthreads();   // protects buffer (cc)%3 before it is re-staged at cc+3
    }

#pragma unroll
    for (int mt = 0; mt < 2; mt++) {
        int r0 = wm + mt * 16 + qrow;
#pragma unroll
        for (int nt = 0; nt < 8; nt++) {
            int col = nbase + wn + nt * 8 + 2 * qk;
            float b0v = bias[col], b1v = bias[col + 1];
            size_t base0 = (mbase + r0) * 256 + col;
            size_t base1 = (mbase + r0 + 8) * 256 + col;
            *(float2*)(C + base0) = make_float2(c[mt][nt][0] + b0v, c[mt][nt][1] + b1v);
            *(float2*)(C + base1) = make_float2(c[mt][nt][2] + b0v, c[mt][nt][3] + b1v);
        }
    }
}

// ---------------- 3) init kernels ----------------
__global__ void sem_init_kernel(const float* __restrict__ mu) {
    int r = blockIdx.x;
    int i = r & 7;
    g_sem_slots[(size_t)r * DD + threadIdx.x] = mu[i * DD + threadIdx.x];
}

__global__ void inst_init_kernel(const float* __restrict__ mu,
                                 const float* __restrict__ sigma,
                                 const float* __restrict__ noise) {
    size_t idx = (size_t)blockIdx.x * 256 + threadIdx.x;
    int d = idx & 255;
    int s = (idx >> 10) & 7;
    g_inst_slots[idx] = mu[s * DD + d] + expf(sigma[s * DD + d]) * noise[idx];
}

// ---------------- 4) double-buffered staged GEMV (4 rows/block) ----------------
__device__ __forceinline__ void gemm4_staged(const float* __restrict__ W,
                                             const float (*__restrict__ in)[DD],
                                             float (*__restrict__ ws)[16][DD],
                                             float* o, int t) {
    o[0] = o[1] = o[2] = o[3] = 0.f;
    int r0 = t >> 6;
    int c0 = (t & 63) * 4;
    float4 pre[4];

#pragma unroll
    for (int j = 0; j < 4; j++)
        pre[j] = *(const float4*)(W + (size_t)(r0 + j * 4) * DD + c0);
#pragma unroll
    for (int j = 0; j < 4; j++)
        *(float4*)&ws[0][r0 + j * 4][c0] = pre[j];
#pragma unroll
    for (int j = 0; j < 4; j++)
        pre[j] = *(const float4*)(W + (size_t)(16 + r0 + j * 4) * DD + c0);
    __syncthreads();

#pragma unroll 1
    for (int ti = 0; ti < 16; ti++) {
        int cur = ti & 1;
        if (ti + 1 < 16) {
#pragma unroll
            for (int j = 0; j < 4; j++)
                *(float4*)&ws[cur ^ 1][r0 + j * 4][c0] = pre[j];
        }
        if (ti + 2 < 16) {
            int d0 = (ti + 2) * 16;
#pragma unroll
            for (int j = 0; j < 4; j++)
                pre[j] = *(const float4*)(W + (size_t)(d0 + r0 + j * 4) * DD + c0);
        }
        int db = ti * 16;
#pragma unroll
        for (int j4 = 0; j4 < 16; j4 += 4) {
            float w0 = ws[cur][j4 + 0][t];
            float w1 = ws[cur][j4 + 1][t];
            float w2 = ws[cur][j4 + 2][t];
            float w3 = ws[cur][j4 + 3][t];
#pragma unroll
            for (int r = 0; r < 4; r++) {
                float4 sv = *(const float4*)&in[r][db + j4];
                o[r] += sv.x * w0 + sv.y * w1 + sv.z * w2 + sv.w * w3;
            }
        }
        __syncthreads();
    }
}

// ---------------- 5) fused MLP + Q + zero (+ optional out sink) ----------------
template<bool DO_MLP, bool DO_Q>
__global__ void __launch_bounds__(256) mlpq_kernel(
    int which, float* __restrict__ out_slots,
    const float* __restrict__ lnff_g, const float* __restrict__ lnff_b,
    const float* __restrict__ W1, const float* __restrict__ b1,
    const float* __restrict__ W2, const float* __restrict__ b2,
    const float* __restrict__ lns_g, const float* __restrict__ lns_b,
    const float* __restrict__ Wq, const float* __restrict__ bq)
{
    __shared__ float s1[4][DD];
    __shared__ float sln[4][DD];
    __shared__ float hs[4][DD];
    __shared__ float ws[2][16][DD];
    __shared__ float rs[8], rs2[8];

    float* slots  = which ? g_inst_slots  : g_sem_slots;
    float* q      = which ? g_inst_q      : g_sem_q;
    float* acc    = which ? g_inst_acc    : g_sem_acc;
    float* rowsum = which ? g_inst_rowsum : g_sem_rowsum;

    int t  = threadIdx.x;
    int r0 = blockIdx.x * 4;

    if (DO_MLP) {
        float gg = lnff_g[t], bb = lnff_b[t];
#pragma unroll
        for (int r = 0; r < 4; r++) {
            int row = r0 + r;
            float v = slots[(size_t)row * DD + t] + acc[(size_t)row * DD + t] / rowsum[row];
            s1[r][t] = v;
            float m, inv;
            block_stats(v, rs, rs2, t, m, inv);
            sln[r][t] = (v - m) * inv * gg + bb;
        }
        __syncthreads();
        float h[4];
        gemm4_staged(W1, sln, ws, h, t);
        float b1v = b1[t];
#pragma unroll
        for (int r = 0; r < 4; r++) hs[r][t] = fmaxf(h[r] + b1v, 0.f);
        __syncthreads();
        float o[4];
        gemm4_staged(W2, hs, ws, o, t);
        float b2v = b2[t];
#pragma unroll
        for (int r = 0; r < 4; r++) {
            float nv = s1[r][t] + o[r] + b2v;
            slots[(size_t)(r0 + r) * DD + t] = nv;
            if (out_slots) out_slots[(size_t)(r0 + r) * DD + t] = nv;
            s1[r][t] = nv;
        }
    } else {
#pragma unroll
        for (int r = 0; r < 4; r++) s1[r][t] = slots[(size_t)(r0 + r) * DD + t];
    }

    if (DO_Q) {
        float gg = lns_g[t], bb = lns_b[t];
#pragma unroll
        for (int r = 0; r < 4; r++) {
            int row = r0 + r;
            float v = s1[r][t];
            float m, inv;
            block_stats(v, rs, rs2, t, m, inv);
            sln[r][t] = (v - m) * inv * gg + bb;
            acc[(size_t)row * DD + t] = 0.f;
            if (t == 0) rowsum[row] = 0.f;
        }
        __syncthreads();
        float qa[4];
        gemm4_staged(Wq, sln, ws, qa, t);
        float qb = bq[t];
#pragma unroll
        for (int r = 0; r < 4; r++)
            q[(size_t)(r0 + r) * DD + t] = qa[r] + qb;
    }
}

// ---------------- mma phase helpers ----------------
template<int MT>
__device__ __forceinline__ void dots_phase(const float* __restrict__ kbase,
                                           const float* __restrict__ qs,
                                           float* __restrict__ kt,
                                           float c[MT][4][4], int t) {
    int lane = t & 31, wid = t >> 5;
    int qrow = lane >> 2, qk = lane & 3;
    int wn = wid * 32;
#pragma unroll
    for (int mt = 0; mt < MT; mt++)
#pragma unroll
        for (int nt = 0; nt < 4; nt++)
#pragma unroll
            for (int i = 0; i < 4; i++) c[mt][nt][i] = 0.f;

    const uint32_t* qsu = (const uint32_t*)qs;
    int srow = t >> 3;
    int sc4  = (t & 7) * 4;

    float4 pre[8];
#pragma unroll
    for (int j = 0; j < 8; j++)
        pre[j] = *(const float4*)(kbase + (size_t)(srow + j * 32) * DD + sc4);
    {
#pragma unroll
        for (int j = 0; j < 8; j++) {
            uint32_t* dst = (uint32_t*)&kt[(srow + j * 32) * KTP + sc4];
            dst[0] = f2tf(pre[j].x); dst[1] = f2tf(pre[j].y);
            dst[2] = f2tf(pre[j].z); dst[3] = f2tf(pre[j].w);
        }
#pragma unroll
        for (int j = 0; j < 8; j++)
            pre[j] = *(const float4*)(kbase + (size_t)(srow + j * 32) * DD + 32 + sc4);
    }
    __syncthreads();

#pragma unroll 1
    for (int cc = 0; cc < 8; cc++) {
        const uint32_t* ktu = (const uint32_t*)(kt + (cc & 1) * RBUF);
        if (cc + 1 < 8) {
            float* nxt = kt + ((cc + 1) & 1) * RBUF;
#pragma unroll
            for (int j = 0; j < 8; j++) {
                uint32_t* dst = (uint32_t*)&nxt[(srow + j * 32) * KTP + sc4];
                dst[0] = f2tf(pre[j].x); dst[1] = f2tf(pre[j].y);
                dst[2] = f2tf(pre[j].z); dst[3] = f2tf(pre[j].w);
            }
        }
        if (cc + 2 < 8) {
            int dc = (cc + 2) * 32;
#pragma unroll
            for (int j = 0; j < 8; j++)
                pre[j] = *(const float4*)(kbase + (size_t)(srow + j * 32) * DD + dc + sc4);
        }
        int dc = cc * 32;
#pragma unroll
        for (int k8 = 0; k8 < 4; k8++) {
            uint32_t a[MT][4], b[4][2];
            int kg = dc + k8 * 8 + qk;
            int kl = k8 * 8 + qk;
#pragma unroll
            for (int mt = 0; mt < MT; mt++) {
                int m0 = mt * 16 + qrow;
                a[mt][0] = qsu[m0 * PQ + kg];
                a[mt][1] = qsu[(m0 + 8) * PQ + kg];
                a[mt][2] = qsu[m0 * PQ + kg + 4];
                a[mt][3] = qsu[(m0 + 8) * PQ + kg + 4];
            }
#pragma unroll
            for (int nt = 0; nt < 4; nt++) {
                int n = wn + nt * 8 + qrow;
                b[nt][0] = ktu[n * KTP + kl];
                b[nt][1] = ktu[n * KTP + kl + 4];
            }
#pragma unroll
            for (int mt = 0; mt < MT; mt++)
#pragma unroll
                for (int nt = 0; nt < 4; nt++)
                    mma_tf32(c[mt][nt], a[mt], b[nt]);
        }
        __syncthreads();
    }
}

template<int MT, int PD>
__device__ __forceinline__ void store_dots(float c[MT][4][4], float* __restrict__ dotm, int t) {
    int lane = t & 31, wid = t >> 5;
    int qrow = lane >> 2, qk = lane & 3;
    int wn = wid * 32;
#pragma unroll
    for (int mt = 0; mt < MT; mt++)
#pragma unroll
        for (int nt = 0; nt < 4; nt++) {
            int tok = wn + nt * 8 + 2 * qk;
            int m0  = mt * 16 + qrow;
            dotm[tok * PD + m0]           = c[mt][nt][0] * SCALE_F;
            dotm[(tok + 1) * PD + m0]     = c[mt][nt][1] * SCALE_F;
            dotm[tok * PD + m0 + 8]       = c[mt][nt][2] * SCALE_F;
            dotm[(tok + 1) * PD + m0 + 8] = c[mt][nt][3] * SCALE_F;
        }
}

template<int MT>
__device__ __forceinline__ void upd_phase(const float* __restrict__ vbase,
                                          const float* __restrict__ atm,
                                          float* __restrict__ vt,
                                          float c[MT][4][4], int t) {
    int lane = t & 31, wid = t >> 5;
    int qrow = lane >> 2, qk = lane & 3;
    int wd = wid * 32;
#pragma unroll
    for (int mt = 0; mt < MT; mt++)
#pragma unroll
        for (int nt = 0; nt < 4; nt++)
#pragma unroll
            for (int i = 0; i < 4; i++) c[mt][nt][i] = 0.f;

    const uint32_t* au = (const uint32_t*)atm;
    int srow = t >> 6;
    int sc4  = (t & 63) * 4;

    float4 pre[8];
#pragma unroll
    for (int j = 0; j < 8; j++)
        pre[j] = *(const float4*)(vbase + (size_t)(srow + j * 4) * DD + sc4);
    {
#pragma unroll
        for (int j = 0; j < 8; j++) {
            uint32_t* dst = (uint32_t*)&vt[(srow + j * 4) * PV + sc4];
            dst[0] = f2tf(pre[j].x); dst[1] = f2tf(pre[j].y);
            dst[2] = f2tf(pre[j].z); dst[3] = f2tf(pre[j].w);
        }
#pragma unroll
        for (int j = 0; j < 8; j++)
            pre[j] = *(const float4*)(vbase + (size_t)(32 + srow + j * 4) * DD + sc4);
    }
    __syncthreads();

#pragma unroll 1
    for (int cc = 0; cc < 8; cc++) {
        const uint32_t* vu = (const uint32_t*)(vt + (cc & 1) * RBUF);
        if (cc + 1 < 8) {
            float* nxt = vt + ((cc + 1) & 1) * RBUF;
#pragma unroll
            for (int j = 0; j < 8; j++) {
                uint32_t* dst = (uint32_t*)&nxt[(srow + j * 4) * PV + sc4];
                dst[0] = f2tf(pre[j].x); dst[1] = f2tf(pre[j].y);
                dst[2] = f2tf(pre[j].z); dst[3] = f2tf(pre[j].w);
            }
        }
        if (cc + 2 < 8) {
            int tc = (cc + 2) * 32;
#pragma unroll
            for (int j = 0; j < 8; j++)
                pre[j] = *(const float4*)(vbase + (size_t)(tc + srow + j * 4) * DD + sc4);
        }
        int tc = cc * 32;
#pragma unroll
        for (int k8 = 0; k8 < 4; k8++) {
            uint32_t a[MT][4], b[4][2];
            int kg = tc + k8 * 8 + qk;
            int kl = k8 * 8 + qk;
#pragma unroll
            for (int mt = 0; mt < MT; mt++) {
                int m0 = mt * 16 + qrow;
                a[mt][0] = au[m0 * PQ + kg];
                a[mt][1] = au[(m0 + 8) * PQ + kg];
                a[mt][2] = au[m0 * PQ + kg + 4];
                a[mt][3] = au[(m0 + 8) * PQ + kg + 4];
            }
#pragma unroll
            for (int nt = 0; nt < 4; nt++) {
                int d = wd + nt * 8 + qrow;
                b[nt][0] = vu[kl * PV + d];
                b[nt][1] = vu[(kl + 4) * PV + d];
            }
#pragma unroll
            for (int mt = 0; mt < MT; mt++)
#pragma unroll
                for (int nt = 0; nt < 4; nt++)
                    mma_tf32(c[mt][nt], a[mt], b[nt]);
        }
        __syncthreads();
    }
}

template<int MT, int NRS>
__device__ __forceinline__ void upd_atomics(float c[MT][4][4], float* __restrict__ gacc,
                                            int slot_base, int t) {
    int lane = t & 31, wid = t >> 5;
    int qrow = lane >> 2, qk = lane & 3;
    int wd = wid * 32;
#pragma unroll
    for (int mt = 0; mt < MT; mt++)
#pragma unroll
        for (int nt = 0; nt < 4; nt++) {
            int d  = wd + nt * 8 + 2 * qk;
            int s0 = mt * 16 + qrow;
            atomicAdd(&gacc[(size_t)(slot_base + s0) * DD + d],     c[mt][nt][0]);
            atomicAdd(&gacc[(size_t)(slot_base + s0) * DD + d + 1], c[mt][nt][1]);
            if (s0 + 8 < NRS) {
                atomicAdd(&gacc[(size_t)(slot_base + s0 + 8) * DD + d],     c[mt][nt][2]);
                atomicAdd(&gacc[(size_t)(slot_base + s0 + 8) * DD + d + 1], c[mt][nt][3]);
            }
        }
}

// ---------------- 6) fused sem (mma) ----------------
__global__ void __launch_bounds__(256) sem_fused_kernel(float* __restrict__ out_dots) {
    extern __shared__ float smem[];
    float* qs   = smem;
    float* reg2 = smem + 16 * PQ;
    const int PD = 17;

    int b  = blockIdx.y;
    int n0 = blockIdx.x * 256;
    int t  = threadIdx.x;
    int n  = n0 + t;

    for (int idx = t; idx < NSL * DD; idx += 256) {
        int r = idx >> 8, cc = idx & 255;
        ((uint32_t*)qs)[r * PQ + cc] = f2tf(g_sem_q[(size_t)b * NSL * DD + idx]);
    }
    for (int idx = t; idx < 8 * DD; idx += 256) {
        int r = idx >> 8, cc = idx & 255;
        qs[(NSL + r) * PQ + cc] = 0.f;
    }

    float c[1][4][4];
    dots_phase<1>(g_k + ((size_t)b * NN + n0) * DD, qs, reg2, c, t);

    store_dots<1, PD>(c, reg2, t);
    __syncthreads();

    float dv[NSL], e[NSL];
    float mx = -1e30f;
#pragma unroll
    for (int i = 0; i < NSL; i++) { dv[i] = reg2[t * PD + i]; mx = fmaxf(mx, dv[i]); }
    float ssum = 0.f;
#pragma unroll
    for (int i = 0; i < NSL; i++) { e[i] = expf(dv[i] - mx); ssum += e[i]; }
    float inv = 1.0f / ssum;

    size_t base = (size_t)b * NSL * NN + n;
    int l = t & 31;
    float at[NSL];
#pragma unroll
    for (int i = 0; i < NSL; i++) {
        at[i] = e[i] * inv + EPS_F;
        if (out_dots) {
            g_sem_dots[base + (size_t)i * NN] = dv[i];
            out_dots[base + (size_t)i * NN]   = dv[i];
        }
        float sv = warp_sum(at[i]);
        if (l == 0) atomicAdd(&g_sem_rowsum[b * NSL + i], sv);
    }

    __syncthreads();
#pragma unroll
    for (int i = 0; i < NSL; i++)
        ((uint32_t*)qs)[i * PQ + t] = f2tf(at[i]);
#pragma unroll
    for (int i = NSL; i < 16; i++)
        qs[i * PQ + t] = 0.f;
    __syncthreads();

    float c2[1][4][4];
    upd_phase<1>(g_v + ((size_t)b * NN + n0) * DD, qs, reg2, c2, t);
    upd_atomics<1, NSL>(c2, g_sem_acc, b * NSL, t);
}

// ---------------- 7) fused inst (mma) ----------------
__global__ void __launch_bounds__(256) inst_fused_kernel(float* __restrict__ out_dots) {
    extern __shared__ float smem[];
    float* qs   = smem;
    float* reg2 = smem + 32 * PQ;
    const int PD = 33;

    int b  = blockIdx.y;
    int n0 = blockIdx.x * 256;
    int t  = threadIdx.x;
    int n  = n0 + t;

    for (int idx = t; idx < 32 * DD; idx += 256) {
        int r = idx >> 8, cc = idx & 255;
        ((uint32_t*)qs)[r * PQ + cc] = f2tf(g_inst_q[(size_t)b * 32 * DD + idx]);
    }

    float c[2][4][4];
    dots_phase<2>(g_k + ((size_t)b * NN + n0) * DD, qs, reg2, c, t);

    store_dots<2, PD>(c, reg2, t);
    __syncthreads();

    float wv[NSL];
    {
        size_t sbase = (size_t)b * NSL * NN + n;
        float sdv[NSL];
        float smx = -1e30f;
#pragma unroll
        for (int i = 0; i < NSL; i++) { sdv[i] = g_sem_dots[sbase + (size_t)i * NN]; smx = fmaxf(smx, sdv[i]); }
        float ss = 0.f;
#pragma unroll
        for (int i = 0; i < NSL; i++) { sdv[i] = expf(sdv[i] - smx); ss += sdv[i]; }
        float sinv = 1.0f / ss;
#pragma unroll
        for (int i = 0; i < NSL; i++) wv[i] = sdv[i] * sinv;
    }

    size_t dbase = (size_t)b * 32 * NN + n;
    int l = t & 31;
    float at[32];
#pragma unroll
    for (int s = 0; s < 8; s++) {
        float dv[NPI], e[NPI];
        float mx = -1e30f;
#pragma unroll
        for (int p = 0; p < NPI; p++) { dv[p] = reg2[t * PD + s * 4 + p]; mx = fmaxf(mx, dv[p]); }
        float ssum = 0.f;
#pragma unroll
        for (int p = 0; p < NPI; p++) { e[p] = expf(dv[p] - mx); ssum += e[p]; }
        float invs = 1.0f / ssum;
#pragma unroll
        for (int p = 0; p < NPI; p++) {
            int sp = s * 4 + p;
            at[sp] = (e[p] * invs + EPS_F) * wv[s];
            if (out_dots) out_dots[dbase + (size_t)sp * NN] = dv[p];
            float sv = warp_sum(at[sp]);
            if (l == 0) atomicAdd(&g_inst_rowsum[b * 32 + sp], sv);
        }
    }

    __syncthreads();
#pragma unroll
    for (int i = 0; i < 32; i++)
        ((uint32_t*)qs)[i * PQ + t] = f2tf(at[i]);
    __syncthreads();

    float c2[2][4][4];
    upd_phase<2>(g_v + ((size_t)b * NN + n0) * DD, qs, reg2, c2, t);
    upd_atomics<2, 32>(c2, g_inst_acc, b * 32, t);
}

// ---------------- launch ----------------
extern "C" void kernel_launch(void* const* d_in, const int* in_sizes, int n_in,
                              void* d_out, int out_size) {
    (void)in_sizes; (void)n_in; (void)out_size;
    const float* inputs      = (const float*)d_in[0];
    const float* noise       = (const float*)d_in[3];
    const float* ln_in_g     = (const float*)d_in[4];
    const float* ln_in_b     = (const float*)d_in[5];
    const float* ln_s_g      = (const float*)d_in[6];
    const float* ln_s_b      = (const float*)d_in[7];
    const float* ln_ff_g     = (const float*)d_in[8];
    const float* ln_ff_b     = (const float*)d_in[9];
    const float* slots_mu    = (const float*)d_in[10];
    const float* slots_sigma = (const float*)d_in[11];
    const float* Wq          = (const float*)d_in[12];
    const float* bq          = (const float*)d_in[13];
    const float* Wk          = (const float*)d_in[14];
    const float* bk          = (const float*)d_in[15];
    const float* Wv          = (const float*)d_in[16];
    const float* bv          = (const float*)d_in[17];
    const float* W1          = (const float*)d_in[18];
    const float* b1          = (const float*)d_in[19];
    const float* W2          = (const float*)d_in[20];
    const float* b2          = (const float*)d_in[21];
    float* out = (float*)d_out;

    const int sem_smem  = (16 * PQ + 2 * RBUF) * 4;   // 90,368 B
    const int inst_smem = (32 * PQ + 2 * RBUF) * 4;   // 107,008 B
    const int gemm_smem = 3 * GBUF * 4;               // 110,592 B
    static int attr_done = 0;
    if (!attr_done) {
        cudaFuncSetAttribute(sem_fused_kernel,  cudaFuncAttributeMaxDynamicSharedMemorySize, sem_smem);
        cudaFuncSetAttribute(inst_fused_kernel, cudaFuncAttributeMaxDynamicSharedMemorySize, inst_smem);
        cudaFuncSetAttribute(gemm_tf32_kernel,  cudaFuncAttributeMaxDynamicSharedMemorySize, gemm_smem);
        attr_done = 1;
    }

    // keep the profiled launch (index 3) = projection GEMM
    prep_b_kernel<<<128, 256>>>(Wk, Wv);
    ln_input_kernel<<<BB * NN, 256>>>(inputs, ln_in_g, ln_in_b);
    sem_init_kernel<<<BB * NSL, 256>>>(slots_mu);

    dim3 gemm_grid(4, 512);
    gemm_tf32_kernel<<<gemm_grid, 256, gemm_smem>>>(bk, bv);

    dim3 bn_grid(16, 16);
    const int SEM_BLKS  = BB * NSL / 4;        // 32
    const int INST_BLKS = BB * NSL * NPI / 4;  // 128

    mlpq_kernel<false, true><<<SEM_BLKS, 256>>>(0, nullptr, ln_ff_g, ln_ff_b, W1, b1, W2, b2,
                                                ln_s_g, ln_s_b, Wq, bq);
    for (int it = 0; it < 3; it++) {
        sem_fused_kernel<<<bn_grid, 256, sem_smem>>>(it == 2 ? out + OUT_SEMDOTS : nullptr);
        if (it < 2)
            mlpq_kernel<true, true><<<SEM_BLKS, 256>>>(0, nullptr, ln_ff_g, ln_ff_b, W1, b1, W2, b2,
                                                       ln_s_g, ln_s_b, Wq, bq);
        else
            mlpq_kernel<true, false><<<SEM_BLKS, 256>>>(0, out + OUT_SEMSLOTS, ln_ff_g, ln_ff_b,
                                                        W1, b1, W2, b2, ln_s_g, ln_s_b, Wq, bq);
    }

    inst_init_kernel<<<BB * NSL * NPI, 256>>>(slots_mu, slots_sigma, noise);

    mlpq_kernel<false, true><<<INST_BLKS, 256>>>(1, nullptr, ln_ff_g, ln_ff_b, W1, b1, W2, b2,
                                                 ln_s_g, ln_s_b, Wq, bq);
    for (int it = 0; it < 3; it++) {
        inst_fused_kernel<<<bn_grid, 256, inst_smem>>>(it == 2 ? out + OUT_INSTDOTS : nullptr);
        if (it < 2)
            mlpq_kernel<true, true><<<INST_BLKS, 256>>>(1, nullptr, ln_ff_g, ln_ff_b, W1, b1, W2, b2,
                                                        ln_s_g, ln_s_b, Wq, bq);
        else
            mlpq_kernel<true, false><<<INST_BLKS, 256>>>(1, out + OUT_INSTSLOTS, ln_ff_g, ln_ff_b,
                                                         W1, b1, W2, b2, ln_s_g, ln_s_b, Wq, bq);
    }
}